// round 14
// baseline (speedup 1.0000x reference)
#include <cuda_runtime.h>
#include <cuda_fp16.h>
#include <cstdint>

#define BB   32
#define NN   2048
#define HH   64
#define OUTD 128
#define KK   16

// ---------------- scratch (static device globals; no runtime allocation) ----
__device__ float g_buf0[BB * NN * HH];
__device__ float g_buf1[BB * NN * HH];
__device__ float g_A[BB * NN * HH];
__device__ float g_C[BB * NN * HH];
__device__ int   g_nbr[BB * NN * KK];
__device__ __align__(16) __half g_xhi[BB * NN * HH];
__device__ float g_sq[BB * NN];
__device__ __align__(16) float4 g_pack[BB * NN];

// ---------------- pack layer-0 xyz + squared norm into float4 ---------------
__global__ __launch_bounds__(128) void pack3_kernel(
    const float* __restrict__ X, float4* __restrict__ P) {
    const int node = blockIdx.x * 128 + threadIdx.x;
    const float* xp = X + (size_t)node * 3;
    float x = xp[0], y = xp[1], z = xp[2];
    float s = fmaf(z, z, fmaf(y, y, fmaf(x, x, 0.f)));
    P[node] = make_float4(x, y, z, s);
}

// ---------------- asm helpers ------------------------------------------------
__device__ __forceinline__ void mma_f16(float* c, const uint32_t* a,
                                        uint32_t b0, uint32_t b1) {
    asm volatile(
        "mma.sync.aligned.m16n8k16.row.col.f32.f16.f16.f32 "
        "{%0,%1,%2,%3},{%4,%5,%6,%7},{%8,%9},{%0,%1,%2,%3};"
        : "+f"(c[0]), "+f"(c[1]), "+f"(c[2]), "+f"(c[3])
        : "r"(a[0]), "r"(a[1]), "r"(a[2]), "r"(a[3]), "r"(b0), "r"(b1));
}
__device__ __forceinline__ void ldsm4(uint32_t* r, uint32_t addr) {
    asm volatile("ldmatrix.sync.aligned.m8n8.x4.shared.b16 {%0,%1,%2,%3}, [%4];"
                 : "=r"(r[0]), "=r"(r[1]), "=r"(r[2]), "=r"(r[3]) : "r"(addr));
}
#define CPA16(d, s) asm volatile("cp.async.ca.shared.global [%0], [%1], 16;" :: "r"(d), "l"(s) : "memory")
#define CPCOMMIT()  asm volatile("cp.async.commit_group;" ::: "memory")
#define CPWAIT()    asm volatile("cp.async.wait_group 0;" ::: "memory")

// ---------------- scalar D=3 kNN (layer 0) ----------------------------------
__global__ __launch_bounds__(128) void knn3_kernel(
    const float4* __restrict__ P, int* __restrict__ nbr) {
    constexpr int NT = NN / 64;
    constexpr int BD = 5;
    __shared__ __align__(16) char SB[2048 + 2560 + 16896];
    float4* sC = (float4*)SB;                 // [2][64]
    int* sIBuf = (int*)(SB + 2048);           // 128*5

    const int b = blockIdx.y;
    const int qbase = blockIdx.x * 64;
    const int tid = threadIdx.x;
    const int selq = tid & 63;
    const int half = tid >> 6;

    const float4 q = P[(size_t)b * NN + qbase + selq];

    float bd[16];
    int bi[16];
#pragma unroll
    for (int t = 0; t < 16; t++) { bd[t] = 3.4028235e38f; bi[t] = 0; }
    float thr = 3.4028235e38f;
    int cnt = 0;

    const uint32_t sC_s = (uint32_t)__cvta_generic_to_shared(sC);

    auto loadC = [&](int ct, int s) {
        if (tid < 64)
            CPA16(sC_s + (s * 64 + tid) * 16, P + (size_t)b * NN + ct * 64 + tid);
        CPCOMMIT();
    };

    auto keyof = [&](const float4& c) {
        return c.w - 2.f * fmaf(q.x, c.x, fmaf(q.y, c.y, q.z * c.z));
    };

    auto flush = [&](int ct, int s) {
        int n = cnt;
        cnt = 0;
        const float4* cb = sC + s * 64;
#pragma unroll 1
        for (int i = 0; i < n; i++) {
            int id = sIBuf[tid * BD + i];
            float k = keyof(cb[id & 63]);
            if (k < bd[15]) {
                bd[15] = k; bi[15] = id;
#pragma unroll
                for (int t = 15; t > 0; t--) {
                    if (bd[t] < bd[t - 1]) {
                        float td = bd[t]; bd[t] = bd[t - 1]; bd[t - 1] = td;
                        int ti = bi[t]; bi[t] = bi[t - 1]; bi[t - 1] = ti;
                    }
                }
            }
        }
        thr = bd[15];
    };

    auto select = [&](int ct, int s) {
        const float4* cb = sC + s * 64 + half * 32;
        const int base = ct * 64 + half * 32;
#pragma unroll 1
        for (int g = 0; g < 8; g++) {
            if (__any_sync(0xffffffffu, cnt >= 2)) flush(ct, s);
            float k0 = keyof(cb[g * 4 + 0]);
            float k1 = keyof(cb[g * 4 + 1]);
            float k2 = keyof(cb[g * 4 + 2]);
            float k3 = keyof(cb[g * 4 + 3]);
            const int ib = base + g * 4;
            if (k0 < thr) { sIBuf[tid * BD + cnt] = ib;     cnt++; }
            if (k1 < thr) { sIBuf[tid * BD + cnt] = ib + 1; cnt++; }
            if (k2 < thr) { sIBuf[tid * BD + cnt] = ib + 2; cnt++; }
            if (k3 < thr) { sIBuf[tid * BD + cnt] = ib + 3; cnt++; }
        }
        if (__any_sync(0xffffffffu, cnt > 0)) flush(ct, s);
    };

    loadC(0, 0);
    CPWAIT();
    __syncthreads();
#pragma unroll 1
    for (int ct = 0; ct < NT; ct++) {
        const int s = ct & 1;
        if (ct + 1 < NT) loadC(ct + 1, s ^ 1);
        select(ct, s);
        if (ct + 1 < NT) CPWAIT();
        __syncthreads();
    }

    float* mD = (float*)SB;
    int* mI = (int*)(SB + 64 * 33 * 4);
    {
        const int basem = selq * 33 + half * 16;
#pragma unroll
        for (int t = 0; t < 16; t++) { mD[basem + t] = bd[t]; mI[basem + t] = bi[t]; }
    }
    __syncthreads();
    if (tid < 64) {
        const float* dA = mD + tid * 33;
        const int* iA = mI + tid * 33;
        int ia = 0, ib2 = 16;
        int* o = nbr + ((size_t)b * NN + qbase + tid) * KK;
#pragma unroll
        for (int r = 0; r < 16; r++) {
            float da = dA[ia], db = dA[ib2];
            int xa = iA[ia], xb = iA[ib2];
            bool ta = (da < db) || (da == db && xa < xb);
            o[r] = ta ? xa : xb;
            if (ta) ia++; else ib2++;
        }
    }
}

// ---------------- tensor-core kNN (fp16 single-pass, 4 CTA/SM) --------------
// 64 queries/block, 64-candidate tiles, padded-row ldsm layout (validated).
// key = sq_j - 2*(qh . ch), pure fp16 product.  smem ~41.2 KB.
// minblocks=4: 128-reg cap (R5 measured 127 regs for this body; the R13
// minblocks=5 cap of 102 regs is the suspected spill source).
template <int DP>
__global__ __launch_bounds__(128, 4) void knn_mma_kernel(
    const __half* __restrict__ Xh, const float* __restrict__ SQ,
    int* __restrict__ nbr) {
    constexpr int NK = DP / 16;
    constexpr int QS = DP + 8;
    constexpr int CS = 68;
    constexpr int NT = NN / 64;
    constexpr int CH = DP / 8;
    constexpr int BD = 10;
    constexpr int PB = 64 * QS * 2;

    extern __shared__ __align__(16) char SB[];
    __half* sQh = (__half*)(SB);
    __half* sCh = (__half*)(SB + PB);
    float* sKey = (float*)(SB + 2 * PB);
    float* sSqc = (float*)(SB + 2 * PB + 64 * CS * 4);
    int*   sIBuf = (int*)(SB + 2 * PB + 64 * CS * 4 + 256);

    const int b = blockIdx.y;
    const int qbase = blockIdx.x * 64;
    const int tid = threadIdx.x;
    const int lane = tid & 31;
    const int warp = tid >> 5;

    {
        const uint4* gh = (const uint4*)(Xh + ((size_t)b * NN + qbase) * DP);
        for (int u = tid; u < 64 * CH; u += 128) {
            int r = u / CH, c = u % CH;
            *(uint4*)(sQh + r * QS + c * 8) = gh[u];
        }
    }

    const uint32_t sQh_s = (uint32_t)__cvta_generic_to_shared(sQh);
    const uint32_t sCh_s = (uint32_t)__cvta_generic_to_shared(sCh);

    const int lrow = (lane & 7) + ((lane >> 3) & 1) * 8;
    const int lcolk = ((lane >> 4) & 1) * 8;

    float bd[16];
    int bi[16];
#pragma unroll
    for (int t = 0; t < 16; t++) { bd[t] = 3.4028235e38f; bi[t] = 0; }
    float thr = 3.4028235e38f;
    int cnt = 0;
    const int selq = tid & 63;
    const int half = tid >> 6;

    auto loadC = [&](int ct) {
        const uint4* gh = (const uint4*)(Xh + ((size_t)b * NN + ct * 64) * DP);
#pragma unroll
        for (int u = tid; u < 64 * CH; u += 128) {
            int r = u / CH, c = u % CH;
            CPA16(sCh_s + (r * QS + c * 8) * 2, gh + u);
        }
        if (tid < 64) sSqc[tid] = SQ[b * NN + ct * 64 + tid];
        CPCOMMIT();
    };

    auto mma_tile = [&]() {
        float acc[8][4];
#pragma unroll
        for (int i = 0; i < 8; i++)
#pragma unroll
            for (int j = 0; j < 4; j++) acc[i][j] = 0.f;

#pragma unroll
        for (int ks = 0; ks < NK; ks++) {
            const int kc = ks * 16 + lcolk;
            uint32_t ah[4];
            ldsm4(ah, sQh_s + ((warp * 16 + lrow) * QS + kc) * 2);
#pragma unroll
            for (int cp = 0; cp < 4; cp++) {
                uint32_t bh[4];
                ldsm4(bh, sCh_s + ((cp * 16 + lrow) * QS + kc) * 2);
                mma_f16(acc[2 * cp], ah, bh[0], bh[2]);
                mma_f16(acc[2 * cp + 1], ah, bh[1], bh[3]);
            }
        }
        const int r0 = warp * 16 + (lane >> 2);
#pragma unroll
        for (int nt = 0; nt < 8; nt++) {
            const int n0 = nt * 8 + (lane & 3) * 2;
            float2 sq2 = *(const float2*)(sSqc + n0);
            *(float2*)(sKey + r0 * CS + n0) =
                make_float2(sq2.x - 2.f * acc[nt][0], sq2.y - 2.f * acc[nt][1]);
            *(float2*)(sKey + (r0 + 8) * CS + n0) =
                make_float2(sq2.x - 2.f * acc[nt][2], sq2.y - 2.f * acc[nt][3]);
        }
    };

    auto flush = [&](int ct) {
        int n = cnt;
        cnt = 0;
        const float* kq = sKey + selq * CS - ct * 64;
#pragma unroll 1
        for (int i = 0; i < n; i++) {
            int id = sIBuf[tid * BD + i];
            float k = kq[id];
            if (k < bd[15]) {
                bd[15] = k; bi[15] = id;
#pragma unroll
                for (int t = 15; t > 0; t--) {
                    if (bd[t] < bd[t - 1]) {
                        float td = bd[t]; bd[t] = bd[t - 1]; bd[t - 1] = td;
                        int ti = bi[t]; bi[t] = bi[t - 1]; bi[t - 1] = ti;
                    }
                }
            }
        }
        thr = bd[15];
    };

    auto select = [&](int ct) {
        const float* kp = sKey + selq * CS + half * 32;
        const int base = ct * 64 + half * 32;
#pragma unroll 1
        for (int g = 0; g < 8; g++) {
            if (((g & 1) == 0) && __any_sync(0xffffffffu, cnt >= 3)) flush(ct);
            float4 v = *(const float4*)(kp + g * 4);
            const int ib = base + g * 4;
            if (v.x < thr) { sIBuf[tid * BD + cnt] = ib;     cnt++; }
            if (v.y < thr) { sIBuf[tid * BD + cnt] = ib + 1; cnt++; }
            if (v.z < thr) { sIBuf[tid * BD + cnt] = ib + 2; cnt++; }
            if (v.w < thr) { sIBuf[tid * BD + cnt] = ib + 3; cnt++; }
        }
        if (__any_sync(0xffffffffu, cnt > 0)) flush(ct);
    };

    loadC(0);
    CPWAIT();
    __syncthreads();
    mma_tile();
#pragma unroll 1
    for (int ct = 1; ct < NT; ct++) {
        __syncthreads();
        loadC(ct);
        select(ct - 1);
        CPWAIT();
        __syncthreads();
        mma_tile();
    }
    __syncthreads();
    select(NT - 1);
    __syncthreads();

    float* mD = sKey;
    int* mI = (int*)((char*)sKey + 64 * 33 * 4);
    {
        const int base = selq * 33 + half * 16;
#pragma unroll
        for (int t = 0; t < 16; t++) { mD[base + t] = bd[t]; mI[base + t] = bi[t]; }
    }
    __syncthreads();
    if (tid < 64) {
        const float* dA = mD + tid * 33;
        const int* iA = mI + tid * 33;
        int ia = 0, ib2 = 16;
        int* o = nbr + ((size_t)b * NN + qbase + tid) * KK;
#pragma unroll
        for (int r = 0; r < 16; r++) {
            float da = dA[ia], db = dA[ib2];
            int xa = iA[ia], xb = iA[ib2];
            bool ta = (da < db) || (da == db && xa < xb);
            o[r] = ta ? xa : xb;
            if (ta) ia++; else ib2++;
        }
    }
}

// ---------------- precompute: register-tiled (4 nodes x 4 h per thread) -----
template <int D>
__global__ __launch_bounds__(256) void precompute_kernel(
    const float* __restrict__ X, const float* __restrict__ w1,
    const float* __restrict__ b1, float* __restrict__ A, float* __restrict__ C) {
    extern __shared__ float PS[];
    float* swd = PS;
    float* swb = PS + D * 64;
    float* sxt = PS + 2 * D * 64;

    const int base = blockIdx.x * 64;
    for (int t = threadIdx.x; t < D * HH; t += 256) {
        float bot = w1[D * HH + t];
        swd[t] = w1[t] - bot;
        swb[t] = bot;
    }
    for (int t = threadIdx.x; t < 64 * D; t += 256) {
        int n = t / D, d = t % D;
        sxt[d * 64 + n] = X[(size_t)base * D + t];
    }
    __syncthreads();

    const int hq = threadIdx.x & 15;
    const int nq = threadIdx.x >> 4;
    const int h0 = hq * 4;
    const float4 bias = *(const float4*)(b1 + h0);

    float a[4][4], c[4][4];
#pragma unroll
    for (int i = 0; i < 4; i++) {
        a[i][0] = bias.x; a[i][1] = bias.y; a[i][2] = bias.z; a[i][3] = bias.w;
        c[i][0] = c[i][1] = c[i][2] = c[i][3] = 0.f;
    }

#pragma unroll
    for (int d = 0; d < D; d++) {
        float4 wd4 = *(const float4*)(swd + d * 64 + h0);
        float4 wb4 = *(const float4*)(swb + d * 64 + h0);
        float4 x4 = *(const float4*)(sxt + d * 64 + nq * 4);
        const float xv[4] = {x4.x, x4.y, x4.z, x4.w};
#pragma unroll
        for (int i = 0; i < 4; i++) {
            a[i][0] = fmaf(xv[i], wd4.x, a[i][0]);
            a[i][1] = fmaf(xv[i], wd4.y, a[i][1]);
            a[i][2] = fmaf(xv[i], wd4.z, a[i][2]);
            a[i][3] = fmaf(xv[i], wd4.w, a[i][3]);
            c[i][0] = fmaf(xv[i], wb4.x, c[i][0]);
            c[i][1] = fmaf(xv[i], wb4.y, c[i][1]);
            c[i][2] = fmaf(xv[i], wb4.z, c[i][2]);
            c[i][3] = fmaf(xv[i], wb4.w, c[i][3]);
        }
    }
#pragma unroll
    for (int i = 0; i < 4; i++) {
        const size_t row = (size_t)(base + nq * 4 + i) * HH + h0;
        *(float4*)(A + row) = make_float4(a[i][0], a[i][1], a[i][2], a[i][3]);
        *(float4*)(C + row) = make_float4(c[i][0], c[i][1], c[i][2], c[i][3]);
    }
}

// ---------------- edge aggregate + output GEMM (64 nodes/block) -------------
// EMIT: also write fp16 features + squared norms for the next layer's kNN.
template <bool EMIT>
__global__ __launch_bounds__(256) void edge_agg_kernel(
    const int* __restrict__ nbr, const float* __restrict__ A,
    const float* __restrict__ C, const float* __restrict__ wo,
    const float* __restrict__ bo, float* __restrict__ out,
    __half* __restrict__ xh, float* __restrict__ sq) {
    __shared__ float swo[HH * HH];
    __shared__ float S[64 * 68];
    __shared__ int snbr[64 * KK];

    const int base = blockIdx.x * 64;
    for (int t = threadIdx.x; t < HH * HH; t += 256) swo[t] = wo[t];
    for (int t = threadIdx.x; t < 64 * KK; t += 256) snbr[t] = nbr[(size_t)base * KK + t];
    __syncthreads();

    const int hq = threadIdx.x & 15;
    const int nq = threadIdx.x >> 4;
    const int h0 = hq * 4;
    const int bofs = ((base >> 11) << 11);
    const float* Cb = C + (size_t)bofs * HH;

#pragma unroll
    for (int i = 0; i < 4; i++) {
        const int n = nq * 4 + i;
        float4 a4 = *(const float4*)(A + (size_t)(base + n) * HH + h0);
        float sx = 0.f, sy = 0.f, sz = 0.f, sw = 0.f;
#pragma unroll
        for (int k = 0; k < KK; k++) {
            int j = snbr[n * KK + k];
            float4 c4 = *(const float4*)(Cb + (size_t)j * HH + h0);
            sx += fmaxf(a4.x + c4.x, 0.f);
            sy += fmaxf(a4.y + c4.y, 0.f);
            sz += fmaxf(a4.z + c4.z, 0.f);
            sw += fmaxf(a4.w + c4.w, 0.f);
        }
        *(float4*)(S + n * 68 + h0) =
            make_float4(sx * (1.f / KK), sy * (1.f / KK), sz * (1.f / KK), sw * (1.f / KK));
    }
    __syncthreads();

    const float4 b4 = *(const float4*)(bo + h0);
    float o[4][4];
#pragma unroll
    for (int i = 0; i < 4; i++) {
        o[i][0] = b4.x; o[i][1] = b4.y; o[i][2] = b4.z; o[i][3] = b4.w;
    }
#pragma unroll 8
    for (int hh = 0; hh < HH; hh++) {
        float4 w4 = *(const float4*)(swo + hh * HH + h0);
#pragma unroll
        for (int i = 0; i < 4; i++) {
            float sv = S[(nq * 4 + i) * 68 + hh];
            o[i][0] = fmaf(sv, w4.x, o[i][0]);
            o[i][1] = fmaf(sv, w4.y, o[i][1]);
            o[i][2] = fmaf(sv, w4.z, o[i][2]);
            o[i][3] = fmaf(sv, w4.w, o[i][3]);
        }
    }
#pragma unroll
    for (int i = 0; i < 4; i++) {
        const int node = base + nq * 4 + i;
        *(float4*)(out + (size_t)node * HH + h0) =
            make_float4(o[i][0], o[i][1], o[i][2], o[i][3]);
        if (EMIT) {
            __half hv[4];
            float ss = 0.f;
#pragma unroll
            for (int j = 0; j < 4; j++) {
                float v = o[i][j];
                ss = fmaf(v, v, ss);
                hv[j] = __float2half(v);
            }
#pragma unroll
            for (int m = 1; m < 16; m <<= 1)
                ss += __shfl_xor_sync(0xffffffffu, ss, m);
            if (hq == 0) sq[node] = ss;
            *(uint2*)(xh + (size_t)node * HH + h0) = *(uint2*)hv;
        }
    }
}

// ---------------- global mean pool + 2-layer head ---------------------------
__global__ __launch_bounds__(128) void head_kernel(
    const float* __restrict__ Xf, const float* __restrict__ fw1,
    const float* __restrict__ fb1, const float* __restrict__ fw2,
    const float* __restrict__ fb2, float* __restrict__ out) {
    int b = blockIdx.x;
    __shared__ float gp[2][HH];
    __shared__ float gv[HH];
    __shared__ float tv[HH];

    int h = threadIdx.x & 63;
    int half = threadIdx.x >> 6;
    float acc = 0.f;
    for (int n = half; n < NN; n += 2)
        acc += Xf[((size_t)b * NN + n) * HH + h];
    gp[half][h] = acc;
    __syncthreads();
    if (threadIdx.x < HH)
        gv[threadIdx.x] = (gp[0][threadIdx.x] + gp[1][threadIdx.x]) * (1.f / NN);
    __syncthreads();
    if (threadIdx.x < HH) {
        float a = fb1[threadIdx.x];
        for (int p = 0; p < HH; p++)
            a = fmaf(gv[p], fw1[p * HH + threadIdx.x], a);
        tv[threadIdx.x] = fmaxf(a, 0.f);
    }
    __syncthreads();
    float o = fb2[threadIdx.x];
    for (int p = 0; p < HH; p++)
        o = fmaf(tv[p], fw2[p * OUTD + threadIdx.x], o);
    out[b * OUTD + threadIdx.x] = o;
}

// ---------------- launch -----------------------------------------------------
static inline int knn_smem_bytes(int DPv) {
    int QSv = DPv + 8;
    return 2 * 64 * QSv * 2 + 64 * 68 * 4 + 256 + 128 * 10 * 4;
}

extern "C" void kernel_launch(void* const* d_in, const int* in_sizes, int n_in,
                              void* d_out, int out_size) {
    (void)in_sizes; (void)n_in; (void)out_size;
    const float* x = (const float*)d_in[0];
    const float* w1a[3] = {(const float*)d_in[1], (const float*)d_in[5], (const float*)d_in[9]};
    const float* b1a[3] = {(const float*)d_in[2], (const float*)d_in[6], (const float*)d_in[10]};
    const float* woa[3] = {(const float*)d_in[3], (const float*)d_in[7], (const float*)d_in[11]};
    const float* boa[3] = {(const float*)d_in[4], (const float*)d_in[8], (const float*)d_in[12]};
    const float* fw1 = (const float*)d_in[13];
    const float* fb1 = (const float*)d_in[14];
    const float* fw2 = (const float*)d_in[15];
    const float* fb2 = (const float*)d_in[16];

    float *buf0, *buf1, *Ab, *Cb, *sq;
    int* nbr;
    __half* xhi;
    float4* pack;
    cudaGetSymbolAddress((void**)&buf0, g_buf0);
    cudaGetSymbolAddress((void**)&buf1, g_buf1);
    cudaGetSymbolAddress((void**)&Ab, g_A);
    cudaGetSymbolAddress((void**)&Cb, g_C);
    cudaGetSymbolAddress((void**)&nbr, g_nbr);
    cudaGetSymbolAddress((void**)&xhi, g_xhi);
    cudaGetSymbolAddress((void**)&sq, g_sq);
    cudaGetSymbolAddress((void**)&pack, g_pack);

    const int smem64 = knn_smem_bytes(64);
    const int pre3  = 3 * 3 * HH * (int)sizeof(float);
    const int pre64 = 3 * 64 * HH * (int)sizeof(float);
    cudaFuncSetAttribute(knn_mma_kernel<64>, cudaFuncAttributeMaxDynamicSharedMemorySize, smem64);
    cudaFuncSetAttribute(precompute_kernel<64>, cudaFuncAttributeMaxDynamicSharedMemorySize, pre64);

    const int CONV_G = BB * NN / 128;
    const dim3 kg(NN / 64, BB);
    const int PRE_G = BB * NN / 64;
    const int AGG_G = BB * NN / 64;

    // layer 0 (D = 3): scalar kNN; edge_agg emits fp16 features for layer 1
    pack3_kernel<<<CONV_G, 128>>>(x, pack);
    knn3_kernel<<<kg, 128>>>(pack, nbr);
    precompute_kernel<3><<<PRE_G, 256, pre3>>>(x, w1a[0], b1a[0], Ab, Cb);
    edge_agg_kernel<true><<<AGG_G, 256>>>(nbr, Ab, Cb, woa[0], boa[0], buf0, xhi, sq);

    // layer 1 (D = 64); edge_agg emits fp16 features for layer 2
    knn_mma_kernel<64><<<kg, 128, smem64>>>(xhi, sq, nbr);
    precompute_kernel<64><<<PRE_G, 256, pre64>>>(buf0, w1a[1], b1a[1], Ab, Cb);
    edge_agg_kernel<true><<<AGG_G, 256>>>(nbr, Ab, Cb, woa[1], boa[1], buf1, xhi, sq);

    // layer 2 (D = 64)
    knn_mma_kernel<64><<<kg, 128, smem64>>>(xhi, sq, nbr);
    precompute_kernel<64><<<PRE_G, 256, pre64>>>(buf1, w1a[2], b1a[2], Ab, Cb);
    edge_agg_kernel<false><<<AGG_G, 256>>>(nbr, Ab, Cb, woa[2], boa[2], buf0, nullptr, nullptr);

    head_kernel<<<BB, 128>>>(buf0, fw1, fb1, fw2, fb2, (float*)d_out);
}

// round 16
// speedup vs baseline: 1.5796x; 1.5796x over previous
#include <cuda_runtime.h>
#include <cuda_fp16.h>
#include <cstdint>

#define BB   32
#define NN   2048
#define HH   64
#define OUTD 128
#define KK   16

// ---------------- scratch (static device globals; no runtime allocation) ----
__device__ float g_buf0[BB * NN * HH];
__device__ float g_buf1[BB * NN * HH];
__device__ float g_A[BB * NN * HH];
__device__ float g_C[BB * NN * HH];
__device__ int   g_nbr[BB * NN * KK];
__device__ __align__(16) __half g_xhi[BB * NN * HH];
__device__ float g_sq[BB * NN];
__device__ __align__(16) float4 g_pack[BB * NN];

// ---------------- pack layer-0 xyz + squared norm into float4 ---------------
__global__ __launch_bounds__(128) void pack3_kernel(
    const float* __restrict__ X, float4* __restrict__ P) {
    const int node = blockIdx.x * 128 + threadIdx.x;
    const float* xp = X + (size_t)node * 3;
    float x = xp[0], y = xp[1], z = xp[2];
    float s = fmaf(z, z, fmaf(y, y, fmaf(x, x, 0.f)));
    P[node] = make_float4(x, y, z, s);
}

// ---------------- asm helpers ------------------------------------------------
__device__ __forceinline__ void mma_f16(float* c, const uint32_t* a,
                                        uint32_t b0, uint32_t b1) {
    asm volatile(
        "mma.sync.aligned.m16n8k16.row.col.f32.f16.f16.f32 "
        "{%0,%1,%2,%3},{%4,%5,%6,%7},{%8,%9},{%0,%1,%2,%3};"
        : "+f"(c[0]), "+f"(c[1]), "+f"(c[2]), "+f"(c[3])
        : "r"(a[0]), "r"(a[1]), "r"(a[2]), "r"(a[3]), "r"(b0), "r"(b1));
}
__device__ __forceinline__ void ldsm4(uint32_t* r, uint32_t addr) {
    asm volatile("ldmatrix.sync.aligned.m8n8.x4.shared.b16 {%0,%1,%2,%3}, [%4];"
                 : "=r"(r[0]), "=r"(r[1]), "=r"(r[2]), "=r"(r[3]) : "r"(addr));
}
#define CPA16(d, s) asm volatile("cp.async.ca.shared.global [%0], [%1], 16;" :: "r"(d), "l"(s) : "memory")
#define CPCOMMIT()  asm volatile("cp.async.commit_group;" ::: "memory")
#define CPWAIT()    asm volatile("cp.async.wait_group 0;" ::: "memory")

// ---------------- scalar D=3 kNN (layer 0) ----------------------------------
__global__ __launch_bounds__(128) void knn3_kernel(
    const float4* __restrict__ P, int* __restrict__ nbr) {
    constexpr int NT = NN / 64;
    constexpr int BD = 5;
    __shared__ __align__(16) char SB[2048 + 2560 + 16896];
    float4* sC = (float4*)SB;                 // [2][64]
    int* sIBuf = (int*)(SB + 2048);           // 128*5

    const int b = blockIdx.y;
    const int qbase = blockIdx.x * 64;
    const int tid = threadIdx.x;
    const int selq = tid & 63;
    const int half = tid >> 6;

    const float4 q = P[(size_t)b * NN + qbase + selq];

    float bd[16];
    int bi[16];
#pragma unroll
    for (int t = 0; t < 16; t++) { bd[t] = 3.4028235e38f; bi[t] = 0; }
    float thr = 3.4028235e38f;
    int cnt = 0;

    const uint32_t sC_s = (uint32_t)__cvta_generic_to_shared(sC);

    auto loadC = [&](int ct, int s) {
        if (tid < 64)
            CPA16(sC_s + (s * 64 + tid) * 16, P + (size_t)b * NN + ct * 64 + tid);
        CPCOMMIT();
    };

    auto keyof = [&](const float4& c) {
        return c.w - 2.f * fmaf(q.x, c.x, fmaf(q.y, c.y, q.z * c.z));
    };

    auto flush = [&](int ct, int s) {
        int n = cnt;
        cnt = 0;
        const float4* cb = sC + s * 64;
#pragma unroll 1
        for (int i = 0; i < n; i++) {
            int id = sIBuf[tid * BD + i];
            float k = keyof(cb[id & 63]);
            if (k < bd[15]) {
                bd[15] = k; bi[15] = id;
#pragma unroll
                for (int t = 15; t > 0; t--) {
                    if (bd[t] < bd[t - 1]) {
                        float td = bd[t]; bd[t] = bd[t - 1]; bd[t - 1] = td;
                        int ti = bi[t]; bi[t] = bi[t - 1]; bi[t - 1] = ti;
                    }
                }
            }
        }
        thr = bd[15];
    };

    auto select = [&](int ct, int s) {
        const float4* cb = sC + s * 64 + half * 32;
        const int base = ct * 64 + half * 32;
#pragma unroll 1
        for (int g = 0; g < 8; g++) {
            if (__any_sync(0xffffffffu, cnt >= 2)) flush(ct, s);
            float k0 = keyof(cb[g * 4 + 0]);
            float k1 = keyof(cb[g * 4 + 1]);
            float k2 = keyof(cb[g * 4 + 2]);
            float k3 = keyof(cb[g * 4 + 3]);
            const int ib = base + g * 4;
            if (k0 < thr) { sIBuf[tid * BD + cnt] = ib;     cnt++; }
            if (k1 < thr) { sIBuf[tid * BD + cnt] = ib + 1; cnt++; }
            if (k2 < thr) { sIBuf[tid * BD + cnt] = ib + 2; cnt++; }
            if (k3 < thr) { sIBuf[tid * BD + cnt] = ib + 3; cnt++; }
        }
        if (__any_sync(0xffffffffu, cnt > 0)) flush(ct, s);
    };

    loadC(0, 0);
    CPWAIT();
    __syncthreads();
#pragma unroll 1
    for (int ct = 0; ct < NT; ct++) {
        const int s = ct & 1;
        if (ct + 1 < NT) loadC(ct + 1, s ^ 1);
        select(ct, s);
        if (ct + 1 < NT) CPWAIT();
        __syncthreads();
    }

    float* mD = (float*)SB;
    int* mI = (int*)(SB + 64 * 33 * 4);
    {
        const int basem = selq * 33 + half * 16;
#pragma unroll
        for (int t = 0; t < 16; t++) { mD[basem + t] = bd[t]; mI[basem + t] = bi[t]; }
    }
    __syncthreads();
    if (tid < 64) {
        const float* dA = mD + tid * 33;
        const int* iA = mI + tid * 33;
        int ia = 0, ib2 = 16;
        int* o = nbr + ((size_t)b * NN + qbase + tid) * KK;
#pragma unroll
        for (int r = 0; r < 16; r++) {
            float da = dA[ia], db = dA[ib2];
            int xa = iA[ia], xb = iA[ib2];
            bool ta = (da < db) || (da == db && xa < xb);
            o[r] = ta ? xa : xb;
            if (ta) ia++; else ib2++;
        }
    }
}

// ---------------- tensor-core kNN (fp16 single-pass, 5 CTA/SM) --------------
// R13 configuration (best measured): minblocks=5, smem ~41.2 KB.
template <int DP>
__global__ __launch_bounds__(128, 5) void knn_mma_kernel(
    const __half* __restrict__ Xh, const float* __restrict__ SQ,
    int* __restrict__ nbr) {
    constexpr int NK = DP / 16;
    constexpr int QS = DP + 8;
    constexpr int CS = 68;
    constexpr int NT = NN / 64;
    constexpr int CH = DP / 8;
    constexpr int BD = 10;
    constexpr int PB = 64 * QS * 2;

    extern __shared__ __align__(16) char SB[];
    __half* sQh = (__half*)(SB);
    __half* sCh = (__half*)(SB + PB);
    float* sKey = (float*)(SB + 2 * PB);
    float* sSqc = (float*)(SB + 2 * PB + 64 * CS * 4);
    int*   sIBuf = (int*)(SB + 2 * PB + 64 * CS * 4 + 256);

    const int b = blockIdx.y;
    const int qbase = blockIdx.x * 64;
    const int tid = threadIdx.x;
    const int lane = tid & 31;
    const int warp = tid >> 5;

    {
        const uint4* gh = (const uint4*)(Xh + ((size_t)b * NN + qbase) * DP);
        for (int u = tid; u < 64 * CH; u += 128) {
            int r = u / CH, c = u % CH;
            *(uint4*)(sQh + r * QS + c * 8) = gh[u];
        }
    }

    const uint32_t sQh_s = (uint32_t)__cvta_generic_to_shared(sQh);
    const uint32_t sCh_s = (uint32_t)__cvta_generic_to_shared(sCh);

    const int lrow = (lane & 7) + ((lane >> 3) & 1) * 8;
    const int lcolk = ((lane >> 4) & 1) * 8;

    float bd[16];
    int bi[16];
#pragma unroll
    for (int t = 0; t < 16; t++) { bd[t] = 3.4028235e38f; bi[t] = 0; }
    float thr = 3.4028235e38f;
    int cnt = 0;
    const int selq = tid & 63;
    const int half = tid >> 6;

    auto loadC = [&](int ct) {
        const uint4* gh = (const uint4*)(Xh + ((size_t)b * NN + ct * 64) * DP);
#pragma unroll
        for (int u = tid; u < 64 * CH; u += 128) {
            int r = u / CH, c = u % CH;
            CPA16(sCh_s + (r * QS + c * 8) * 2, gh + u);
        }
        if (tid < 64) sSqc[tid] = SQ[b * NN + ct * 64 + tid];
        CPCOMMIT();
    };

    auto mma_tile = [&]() {
        float acc[8][4];
#pragma unroll
        for (int i = 0; i < 8; i++)
#pragma unroll
            for (int j = 0; j < 4; j++) acc[i][j] = 0.f;

#pragma unroll
        for (int ks = 0; ks < NK; ks++) {
            const int kc = ks * 16 + lcolk;
            uint32_t ah[4];
            ldsm4(ah, sQh_s + ((warp * 16 + lrow) * QS + kc) * 2);
#pragma unroll
            for (int cp = 0; cp < 4; cp++) {
                uint32_t bh[4];
                ldsm4(bh, sCh_s + ((cp * 16 + lrow) * QS + kc) * 2);
                mma_f16(acc[2 * cp], ah, bh[0], bh[2]);
                mma_f16(acc[2 * cp + 1], ah, bh[1], bh[3]);
            }
        }
        const int r0 = warp * 16 + (lane >> 2);
#pragma unroll
        for (int nt = 0; nt < 8; nt++) {
            const int n0 = nt * 8 + (lane & 3) * 2;
            float2 sq2 = *(const float2*)(sSqc + n0);
            *(float2*)(sKey + r0 * CS + n0) =
                make_float2(sq2.x - 2.f * acc[nt][0], sq2.y - 2.f * acc[nt][1]);
            *(float2*)(sKey + (r0 + 8) * CS + n0) =
                make_float2(sq2.x - 2.f * acc[nt][2], sq2.y - 2.f * acc[nt][3]);
        }
    };

    auto flush = [&](int ct) {
        int n = cnt;
        cnt = 0;
        const float* kq = sKey + selq * CS - ct * 64;
#pragma unroll 1
        for (int i = 0; i < n; i++) {
            int id = sIBuf[tid * BD + i];
            float k = kq[id];
            if (k < bd[15]) {
                bd[15] = k; bi[15] = id;
#pragma unroll
                for (int t = 15; t > 0; t--) {
                    if (bd[t] < bd[t - 1]) {
                        float td = bd[t]; bd[t] = bd[t - 1]; bd[t - 1] = td;
                        int ti = bi[t]; bi[t] = bi[t - 1]; bi[t - 1] = ti;
                    }
                }
            }
        }
        thr = bd[15];
    };

    auto select = [&](int ct) {
        const float* kp = sKey + selq * CS + half * 32;
        const int base = ct * 64 + half * 32;
#pragma unroll 1
        for (int g = 0; g < 8; g++) {
            if (((g & 1) == 0) && __any_sync(0xffffffffu, cnt >= 3)) flush(ct);
            float4 v = *(const float4*)(kp + g * 4);
            const int ib = base + g * 4;
            if (v.x < thr) { sIBuf[tid * BD + cnt] = ib;     cnt++; }
            if (v.y < thr) { sIBuf[tid * BD + cnt] = ib + 1; cnt++; }
            if (v.z < thr) { sIBuf[tid * BD + cnt] = ib + 2; cnt++; }
            if (v.w < thr) { sIBuf[tid * BD + cnt] = ib + 3; cnt++; }
        }
        if (__any_sync(0xffffffffu, cnt > 0)) flush(ct);
    };

    loadC(0);
    CPWAIT();
    __syncthreads();
    mma_tile();
#pragma unroll 1
    for (int ct = 1; ct < NT; ct++) {
        __syncthreads();
        loadC(ct);
        select(ct - 1);
        CPWAIT();
        __syncthreads();
        mma_tile();
    }
    __syncthreads();
    select(NT - 1);
    __syncthreads();

    float* mD = sKey;
    int* mI = (int*)((char*)sKey + 64 * 33 * 4);
    {
        const int base = selq * 33 + half * 16;
#pragma unroll
        for (int t = 0; t < 16; t++) { mD[base + t] = bd[t]; mI[base + t] = bi[t]; }
    }
    __syncthreads();
    if (tid < 64) {
        const float* dA = mD + tid * 33;
        const int* iA = mI + tid * 33;
        int ia = 0, ib2 = 16;
        int* o = nbr + ((size_t)b * NN + qbase + tid) * KK;
#pragma unroll
        for (int r = 0; r < 16; r++) {
            float da = dA[ia], db = dA[ib2];
            int xa = iA[ia], xb = iA[ib2];
            bool ta = (da < db) || (da == db && xa < xb);
            o[r] = ta ? xa : xb;
            if (ta) ia++; else ib2++;
        }
    }
}

// ---------------- precompute: register-tiled (4 nodes x 4 h per thread) -----
template <int D>
__global__ __launch_bounds__(256) void precompute_kernel(
    const float* __restrict__ X, const float* __restrict__ w1,
    const float* __restrict__ b1, float* __restrict__ A, float* __restrict__ C) {
    extern __shared__ float PS[];
    float* swd = PS;
    float* swb = PS + D * 64;
    float* sxt = PS + 2 * D * 64;

    const int base = blockIdx.x * 64;
    for (int t = threadIdx.x; t < D * HH; t += 256) {
        float bot = w1[D * HH + t];
        swd[t] = w1[t] - bot;
        swb[t] = bot;
    }
    for (int t = threadIdx.x; t < 64 * D; t += 256) {
        int n = t / D, d = t % D;
        sxt[d * 64 + n] = X[(size_t)base * D + t];
    }
    __syncthreads();

    const int hq = threadIdx.x & 15;
    const int nq = threadIdx.x >> 4;
    const int h0 = hq * 4;
    const float4 bias = *(const float4*)(b1 + h0);

    float a[4][4], c[4][4];
#pragma unroll
    for (int i = 0; i < 4; i++) {
        a[i][0] = bias.x; a[i][1] = bias.y; a[i][2] = bias.z; a[i][3] = bias.w;
        c[i][0] = c[i][1] = c[i][2] = c[i][3] = 0.f;
    }

#pragma unroll
    for (int d = 0; d < D; d++) {
        float4 wd4 = *(const float4*)(swd + d * 64 + h0);
        float4 wb4 = *(const float4*)(swb + d * 64 + h0);
        float4 x4 = *(const float4*)(sxt + d * 64 + nq * 4);
        const float xv[4] = {x4.x, x4.y, x4.z, x4.w};
#pragma unroll
        for (int i = 0; i < 4; i++) {
            a[i][0] = fmaf(xv[i], wd4.x, a[i][0]);
            a[i][1] = fmaf(xv[i], wd4.y, a[i][1]);
            a[i][2] = fmaf(xv[i], wd4.z, a[i][2]);
            a[i][3] = fmaf(xv[i], wd4.w, a[i][3]);
            c[i][0] = fmaf(xv[i], wb4.x, c[i][0]);
            c[i][1] = fmaf(xv[i], wb4.y, c[i][1]);
            c[i][2] = fmaf(xv[i], wb4.z, c[i][2]);
            c[i][3] = fmaf(xv[i], wb4.w, c[i][3]);
        }
    }
#pragma unroll
    for (int i = 0; i < 4; i++) {
        const size_t row = (size_t)(base + nq * 4 + i) * HH + h0;
        *(float4*)(A + row) = make_float4(a[i][0], a[i][1], a[i][2], a[i][3]);
        *(float4*)(C + row) = make_float4(c[i][0], c[i][1], c[i][2], c[i][3]);
    }
}

// ---------------- edge aggregate + output GEMM (64 nodes/block) -------------
// EMIT: also write fp16 features + squared norms for the next layer's kNN.
template <bool EMIT>
__global__ __launch_bounds__(256) void edge_agg_kernel(
    const int* __restrict__ nbr, const float* __restrict__ A,
    const float* __restrict__ C, const float* __restrict__ wo,
    const float* __restrict__ bo, float* __restrict__ out,
    __half* __restrict__ xh, float* __restrict__ sq) {
    __shared__ float swo[HH * HH];
    __shared__ float S[64 * 68];
    __shared__ int snbr[64 * KK];

    const int base = blockIdx.x * 64;
    for (int t = threadIdx.x; t < HH * HH; t += 256) swo[t] = wo[t];
    for (int t = threadIdx.x; t < 64 * KK; t += 256) snbr[t] = nbr[(size_t)base * KK + t];
    __syncthreads();

    const int hq = threadIdx.x & 15;
    const int nq = threadIdx.x >> 4;
    const int h0 = hq * 4;
    const int bofs = ((base >> 11) << 11);
    const float* Cb = C + (size_t)bofs * HH;

#pragma unroll
    for (int i = 0; i < 4; i++) {
        const int n = nq * 4 + i;
        float4 a4 = *(const float4*)(A + (size_t)(base + n) * HH + h0);
        float sx = 0.f, sy = 0.f, sz = 0.f, sw = 0.f;
#pragma unroll
        for (int k = 0; k < KK; k++) {
            int j = snbr[n * KK + k];
            float4 c4 = *(const float4*)(Cb + (size_t)j * HH + h0);
            sx += fmaxf(a4.x + c4.x, 0.f);
            sy += fmaxf(a4.y + c4.y, 0.f);
            sz += fmaxf(a4.z + c4.z, 0.f);
            sw += fmaxf(a4.w + c4.w, 0.f);
        }
        *(float4*)(S + n * 68 + h0) =
            make_float4(sx * (1.f / KK), sy * (1.f / KK), sz * (1.f / KK), sw * (1.f / KK));
    }
    __syncthreads();

    const float4 b4 = *(const float4*)(bo + h0);
    float o[4][4];
#pragma unroll
    for (int i = 0; i < 4; i++) {
        o[i][0] = b4.x; o[i][1] = b4.y; o[i][2] = b4.z; o[i][3] = b4.w;
    }
#pragma unroll 8
    for (int hh = 0; hh < HH; hh++) {
        float4 w4 = *(const float4*)(swo + hh * HH + h0);
#pragma unroll
        for (int i = 0; i < 4; i++) {
            float sv = S[(nq * 4 + i) * 68 + hh];
            o[i][0] = fmaf(sv, w4.x, o[i][0]);
            o[i][1] = fmaf(sv, w4.y, o[i][1]);
            o[i][2] = fmaf(sv, w4.z, o[i][2]);
            o[i][3] = fmaf(sv, w4.w, o[i][3]);
        }
    }
#pragma unroll
    for (int i = 0; i < 4; i++) {
        const int node = base + nq * 4 + i;
        *(float4*)(out + (size_t)node * HH + h0) =
            make_float4(o[i][0], o[i][1], o[i][2], o[i][3]);
        if (EMIT) {
            __half hv[4];
            float ss = 0.f;
#pragma unroll
            for (int j = 0; j < 4; j++) {
                float v = o[i][j];
                ss = fmaf(v, v, ss);
                hv[j] = __float2half(v);
            }
#pragma unroll
            for (int m = 1; m < 16; m <<= 1)
                ss += __shfl_xor_sync(0xffffffffu, ss, m);
            if (hq == 0) sq[node] = ss;
            *(uint2*)(xh + (size_t)node * HH + h0) = *(uint2*)hv;
        }
    }
}

// ---------------- global mean pool + 2-layer head ---------------------------
__global__ __launch_bounds__(128) void head_kernel(
    const float* __restrict__ Xf, const float* __restrict__ fw1,
    const float* __restrict__ fb1, const float* __restrict__ fw2,
    const float* __restrict__ fb2, float* __restrict__ out) {
    int b = blockIdx.x;
    __shared__ float gp[2][HH];
    __shared__ float gv[HH];
    __shared__ float tv[HH];

    int h = threadIdx.x & 63;
    int half = threadIdx.x >> 6;
    float acc = 0.f;
    for (int n = half; n < NN; n += 2)
        acc += Xf[((size_t)b * NN + n) * HH + h];
    gp[half][h] = acc;
    __syncthreads();
    if (threadIdx.x < HH)
        gv[threadIdx.x] = (gp[0][threadIdx.x] + gp[1][threadIdx.x]) * (1.f / NN);
    __syncthreads();
    if (threadIdx.x < HH) {
        float a = fb1[threadIdx.x];
        for (int p = 0; p < HH; p++)
            a = fmaf(gv[p], fw1[p * HH + threadIdx.x], a);
        tv[threadIdx.x] = fmaxf(a, 0.f);
    }
    __syncthreads();
    float o = fb2[threadIdx.x];
    for (int p = 0; p < HH; p++)
        o = fmaf(tv[p], fw2[p * OUTD + threadIdx.x], o);
    out[b * OUTD + threadIdx.x] = o;
}

// ---------------- launch -----------------------------------------------------
static inline int knn_smem_bytes(int DPv) {
    int QSv = DPv + 8;
    return 2 * 64 * QSv * 2 + 64 * 68 * 4 + 256 + 128 * 10 * 4;
}

extern "C" void kernel_launch(void* const* d_in, const int* in_sizes, int n_in,
                              void* d_out, int out_size) {
    (void)in_sizes; (void)n_in; (void)out_size;
    const float* x = (const float*)d_in[0];
    const float* w1a[3] = {(const float*)d_in[1], (const float*)d_in[5], (const float*)d_in[9]};
    const float* b1a[3] = {(const float*)d_in[2], (const float*)d_in[6], (const float*)d_in[10]};
    const float* woa[3] = {(const float*)d_in[3], (const float*)d_in[7], (const float*)d_in[11]};
    const float* boa[3] = {(const float*)d_in[4], (const float*)d_in[8], (const float*)d_in[12]};
    const float* fw1 = (const float*)d_in[13];
    const float* fb1 = (const float*)d_in[14];
    const float* fw2 = (const float*)d_in[15];
    const float* fb2 = (const float*)d_in[16];

    float *buf0, *buf1, *Ab, *Cb, *sq;
    int* nbr;
    __half* xhi;
    float4* pack;
    cudaGetSymbolAddress((void**)&buf0, g_buf0);
    cudaGetSymbolAddress((void**)&buf1, g_buf1);
    cudaGetSymbolAddress((void**)&Ab, g_A);
    cudaGetSymbolAddress((void**)&Cb, g_C);
    cudaGetSymbolAddress((void**)&nbr, g_nbr);
    cudaGetSymbolAddress((void**)&xhi, g_xhi);
    cudaGetSymbolAddress((void**)&sq, g_sq);
    cudaGetSymbolAddress((void**)&pack, g_pack);

    // one-time side-stream + events (host objects only; no device allocation)
    static cudaStream_t s1 = nullptr;
    static cudaEvent_t evF[3], evJ[3];
    if (!s1) {
        cudaStreamCreateWithFlags(&s1, cudaStreamNonBlocking);
        for (int i = 0; i < 3; i++) {
            cudaEventCreateWithFlags(&evF[i], cudaEventDisableTiming);
            cudaEventCreateWithFlags(&evJ[i], cudaEventDisableTiming);
        }
    }

    const int smem64 = knn_smem_bytes(64);
    const int pre3  = 3 * 3 * HH * (int)sizeof(float);
    const int pre64 = 3 * 64 * HH * (int)sizeof(float);
    cudaFuncSetAttribute(knn_mma_kernel<64>, cudaFuncAttributeMaxDynamicSharedMemorySize, smem64);
    cudaFuncSetAttribute(precompute_kernel<64>, cudaFuncAttributeMaxDynamicSharedMemorySize, pre64);

    const int CONV_G = BB * NN / 128;
    const dim3 kg(NN / 64, BB);
    const int PRE_G = BB * NN / 64;
    const int AGG_G = BB * NN / 64;

    // ---- layer 0 (D = 3): pre3 on side stream overlaps pack3+knn3 ----
    cudaEventRecord(evF[0], 0);
    cudaStreamWaitEvent(s1, evF[0], 0);
    precompute_kernel<3><<<PRE_G, 256, pre3, s1>>>(x, w1a[0], b1a[0], Ab, Cb);
    cudaEventRecord(evJ[0], s1);

    pack3_kernel<<<CONV_G, 128>>>(x, pack);
    knn3_kernel<<<kg, 128>>>(pack, nbr);
    cudaStreamWaitEvent(0, evJ[0], 0);
    edge_agg_kernel<true><<<AGG_G, 256>>>(nbr, Ab, Cb, woa[0], boa[0], buf0, xhi, sq);

    // ---- layer 1: pre64 on side stream overlaps knn64 ----
    cudaEventRecord(evF[1], 0);
    cudaStreamWaitEvent(s1, evF[1], 0);
    precompute_kernel<64><<<PRE_G, 256, pre64, s1>>>(buf0, w1a[1], b1a[1], Ab, Cb);
    cudaEventRecord(evJ[1], s1);

    knn_mma_kernel<64><<<kg, 128, smem64>>>(xhi, sq, nbr);
    cudaStreamWaitEvent(0, evJ[1], 0);
    edge_agg_kernel<true><<<AGG_G, 256>>>(nbr, Ab, Cb, woa[1], boa[1], buf1, xhi, sq);

    // ---- layer 2 ----
    cudaEventRecord(evF[2], 0);
    cudaStreamWaitEvent(s1, evF[2], 0);
    precompute_kernel<64><<<PRE_G, 256, pre64, s1>>>(buf1, w1a[2], b1a[2], Ab, Cb);
    cudaEventRecord(evJ[2], s1);

    knn_mma_kernel<64><<<kg, 128, smem64>>>(xhi, sq, nbr);
    cudaStreamWaitEvent(0, evJ[2], 0);
    edge_agg_kernel<false><<<AGG_G, 256>>>(nbr, Ab, Cb, woa[2], boa[2], buf0, nullptr, nullptr);

    head_kernel<<<BB, 128>>>(buf0, fw1, fb1, fw2, fb2, (float*)d_out);
}

// round 17
// speedup vs baseline: 1.6155x; 1.0227x over previous
#include <cuda_runtime.h>
#include <cuda_fp16.h>
#include <cstdint>

#define BB   32
#define NN   2048
#define HH   64
#define OUTD 128
#define KK   16

// ---------------- scratch (static device globals; no runtime allocation) ----
__device__ float g_buf0[BB * NN * HH];
__device__ float g_buf1[BB * NN * HH];
__device__ float g_A[BB * NN * HH];
__device__ float g_C[BB * NN * HH];
__device__ int   g_nbr[BB * NN * KK];
__device__ __align__(16) __half g_xhi[BB * NN * HH];
__device__ float g_sq[BB * NN];
__device__ __align__(16) float4 g_pack[BB * NN];

// ---------------- pack layer-0 xyz + squared norm into float4 ---------------
__global__ __launch_bounds__(128) void pack3_kernel(
    const float* __restrict__ X, float4* __restrict__ P) {
    const int node = blockIdx.x * 128 + threadIdx.x;
    const float* xp = X + (size_t)node * 3;
    float x = xp[0], y = xp[1], z = xp[2];
    float s = fmaf(z, z, fmaf(y, y, fmaf(x, x, 0.f)));
    P[node] = make_float4(x, y, z, s);
}

// ---------------- asm helpers ------------------------------------------------
__device__ __forceinline__ void mma_f16(float* c, const uint32_t* a,
                                        uint32_t b0, uint32_t b1) {
    asm volatile(
        "mma.sync.aligned.m16n8k16.row.col.f32.f16.f16.f32 "
        "{%0,%1,%2,%3},{%4,%5,%6,%7},{%8,%9},{%0,%1,%2,%3};"
        : "+f"(c[0]), "+f"(c[1]), "+f"(c[2]), "+f"(c[3])
        : "r"(a[0]), "r"(a[1]), "r"(a[2]), "r"(a[3]), "r"(b0), "r"(b1));
}
__device__ __forceinline__ void ldsm4(uint32_t* r, uint32_t addr) {
    asm volatile("ldmatrix.sync.aligned.m8n8.x4.shared.b16 {%0,%1,%2,%3}, [%4];"
                 : "=r"(r[0]), "=r"(r[1]), "=r"(r[2]), "=r"(r[3]) : "r"(addr));
}
#define CPA16(d, s) asm volatile("cp.async.ca.shared.global [%0], [%1], 16;" :: "r"(d), "l"(s) : "memory")
#define CPCOMMIT()  asm volatile("cp.async.commit_group;" ::: "memory")
#define CPWAIT()    asm volatile("cp.async.wait_group 0;" ::: "memory")

// ---------------- scalar D=3 kNN (layer 0) ----------------------------------
__global__ __launch_bounds__(128) void knn3_kernel(
    const float4* __restrict__ P, int* __restrict__ nbr) {
    constexpr int NT = NN / 64;
    constexpr int BD = 5;
    __shared__ __align__(16) char SB[2048 + 2560 + 16896];
    float4* sC = (float4*)SB;                 // [2][64]
    int* sIBuf = (int*)(SB + 2048);           // 128*5

    const int b = blockIdx.y;
    const int qbase = blockIdx.x * 64;
    const int tid = threadIdx.x;
    const int selq = tid & 63;
    const int half = tid >> 6;

    const float4 q = P[(size_t)b * NN + qbase + selq];

    float bd[16];
    int bi[16];
#pragma unroll
    for (int t = 0; t < 16; t++) { bd[t] = 3.4028235e38f; bi[t] = 0; }
    float thr = 3.4028235e38f;
    int cnt = 0;

    const uint32_t sC_s = (uint32_t)__cvta_generic_to_shared(sC);

    auto loadC = [&](int ct, int s) {
        if (tid < 64)
            CPA16(sC_s + (s * 64 + tid) * 16, P + (size_t)b * NN + ct * 64 + tid);
        CPCOMMIT();
    };

    auto keyof = [&](const float4& c) {
        return c.w - 2.f * fmaf(q.x, c.x, fmaf(q.y, c.y, q.z * c.z));
    };

    auto flush = [&](int ct, int s) {
        int n = cnt;
        cnt = 0;
        const float4* cb = sC + s * 64;
#pragma unroll 1
        for (int i = 0; i < n; i++) {
            int id = sIBuf[tid * BD + i];
            float k = keyof(cb[id & 63]);
            if (k < bd[15]) {
                bd[15] = k; bi[15] = id;
#pragma unroll
                for (int t = 15; t > 0; t--) {
                    if (bd[t] < bd[t - 1]) {
                        float td = bd[t]; bd[t] = bd[t - 1]; bd[t - 1] = td;
                        int ti = bi[t]; bi[t] = bi[t - 1]; bi[t - 1] = ti;
                    }
                }
            }
        }
        thr = bd[15];
    };

    auto select = [&](int ct, int s) {
        const float4* cb = sC + s * 64 + half * 32;
        const int base = ct * 64 + half * 32;
#pragma unroll 1
        for (int g = 0; g < 8; g++) {
            if (__any_sync(0xffffffffu, cnt >= 2)) flush(ct, s);
            float k0 = keyof(cb[g * 4 + 0]);
            float k1 = keyof(cb[g * 4 + 1]);
            float k2 = keyof(cb[g * 4 + 2]);
            float k3 = keyof(cb[g * 4 + 3]);
            const int ib = base + g * 4;
            if (k0 < thr) { sIBuf[tid * BD + cnt] = ib;     cnt++; }
            if (k1 < thr) { sIBuf[tid * BD + cnt] = ib + 1; cnt++; }
            if (k2 < thr) { sIBuf[tid * BD + cnt] = ib + 2; cnt++; }
            if (k3 < thr) { sIBuf[tid * BD + cnt] = ib + 3; cnt++; }
        }
        if (__any_sync(0xffffffffu, cnt > 0)) flush(ct, s);
    };

    loadC(0, 0);
    CPWAIT();
    __syncthreads();
#pragma unroll 1
    for (int ct = 0; ct < NT; ct++) {
        const int s = ct & 1;
        if (ct + 1 < NT) loadC(ct + 1, s ^ 1);
        select(ct, s);
        if (ct + 1 < NT) CPWAIT();
        __syncthreads();
    }

    float* mD = (float*)SB;
    int* mI = (int*)(SB + 64 * 33 * 4);
    {
        const int basem = selq * 33 + half * 16;
#pragma unroll
        for (int t = 0; t < 16; t++) { mD[basem + t] = bd[t]; mI[basem + t] = bi[t]; }
    }
    __syncthreads();
    if (tid < 64) {
        const float* dA = mD + tid * 33;
        const int* iA = mI + tid * 33;
        int ia = 0, ib2 = 16;
        int* o = nbr + ((size_t)b * NN + qbase + tid) * KK;
#pragma unroll
        for (int r = 0; r < 16; r++) {
            float da = dA[ia], db = dA[ib2];
            int xa = iA[ia], xb = iA[ib2];
            bool ta = (da < db) || (da == db && xa < xb);
            o[r] = ta ? xa : xb;
            if (ta) ia++; else ib2++;
        }
    }
}

// ---------------- tensor-core kNN (fp16 single-pass, 5 CTA/SM) --------------
// A fragments hoisted to registers (tile-invariant); select with 2 ballots/tile
// (depth-16 buffer, mid+end flush).  smem ~44.3 KB.
template <int DP>
__global__ __launch_bounds__(128, 5) void knn_mma_kernel(
    const __half* __restrict__ Xh, const float* __restrict__ SQ,
    int* __restrict__ nbr) {
    constexpr int NK = DP / 16;
    constexpr int QS = DP + 8;
    constexpr int CS = 68;
    constexpr int NT = NN / 64;
    constexpr int CH = DP / 8;
    constexpr int BD = 16;
    constexpr int PB = 64 * QS * 2;

    extern __shared__ __align__(16) char SB[];
    __half* sQh = (__half*)(SB);
    __half* sCh = (__half*)(SB + PB);
    float* sKey = (float*)(SB + 2 * PB);
    float* sSqc = (float*)(SB + 2 * PB + 64 * CS * 4);
    int*   sIBuf = (int*)(SB + 2 * PB + 64 * CS * 4 + 256);

    const int b = blockIdx.y;
    const int qbase = blockIdx.x * 64;
    const int tid = threadIdx.x;
    const int lane = tid & 31;
    const int warp = tid >> 5;

    {
        const uint4* gh = (const uint4*)(Xh + ((size_t)b * NN + qbase) * DP);
        for (int u = tid; u < 64 * CH; u += 128) {
            int r = u / CH, c = u % CH;
            *(uint4*)(sQh + r * QS + c * 8) = gh[u];
        }
    }

    const uint32_t sQh_s = (uint32_t)__cvta_generic_to_shared(sQh);
    const uint32_t sCh_s = (uint32_t)__cvta_generic_to_shared(sCh);

    const int lrow = (lane & 7) + ((lane >> 3) & 1) * 8;
    const int lcolk = ((lane >> 4) & 1) * 8;

    float bd[16];
    int bi[16];
#pragma unroll
    for (int t = 0; t < 16; t++) { bd[t] = 3.4028235e38f; bi[t] = 0; }
    float thr = 3.4028235e38f;
    int cnt = 0;
    const int selq = tid & 63;
    const int half = tid >> 6;

    auto loadC = [&](int ct) {
        const uint4* gh = (const uint4*)(Xh + ((size_t)b * NN + ct * 64) * DP);
#pragma unroll
        for (int u = tid; u < 64 * CH; u += 128) {
            int r = u / CH, c = u % CH;
            CPA16(sCh_s + (r * QS + c * 8) * 2, gh + u);
        }
        if (tid < 64) sSqc[tid] = SQ[b * NN + ct * 64 + tid];
        CPCOMMIT();
    };

    // ---- pipeline prologue: first C tile + hoist A fragments ----
    loadC(0);
    CPWAIT();
    __syncthreads();

    uint32_t ahh[NK][4];
#pragma unroll
    for (int ks = 0; ks < NK; ks++)
        ldsm4(ahh[ks], sQh_s + ((warp * 16 + lrow) * QS + ks * 16 + lcolk) * 2);

    auto mma_tile = [&]() {
        float acc[8][4];
#pragma unroll
        for (int i = 0; i < 8; i++)
#pragma unroll
            for (int j = 0; j < 4; j++) acc[i][j] = 0.f;

#pragma unroll
        for (int ks = 0; ks < NK; ks++) {
            const int kc = ks * 16 + lcolk;
#pragma unroll
            for (int cp = 0; cp < 4; cp++) {
                uint32_t bh[4];
                ldsm4(bh, sCh_s + ((cp * 16 + lrow) * QS + kc) * 2);
                mma_f16(acc[2 * cp], ahh[ks], bh[0], bh[2]);
                mma_f16(acc[2 * cp + 1], ahh[ks], bh[1], bh[3]);
            }
        }
        const int r0 = warp * 16 + (lane >> 2);
#pragma unroll
        for (int nt = 0; nt < 8; nt++) {
            const int n0 = nt * 8 + (lane & 3) * 2;
            float2 sq2 = *(const float2*)(sSqc + n0);
            *(float2*)(sKey + r0 * CS + n0) =
                make_float2(sq2.x - 2.f * acc[nt][0], sq2.y - 2.f * acc[nt][1]);
            *(float2*)(sKey + (r0 + 8) * CS + n0) =
                make_float2(sq2.x - 2.f * acc[nt][2], sq2.y - 2.f * acc[nt][3]);
        }
    };

    auto flush = [&](int ct) {
        int n = cnt;
        cnt = 0;
        const float* kq = sKey + selq * CS - ct * 64;
#pragma unroll 1
        for (int i = 0; i < n; i++) {
            int id = sIBuf[tid * BD + i];
            float k = kq[id];
            if (k < bd[15]) {
                bd[15] = k; bi[15] = id;
#pragma unroll
                for (int t = 15; t > 0; t--) {
                    if (bd[t] < bd[t - 1]) {
                        float td = bd[t]; bd[t] = bd[t - 1]; bd[t - 1] = td;
                        int ti = bi[t]; bi[t] = bi[t - 1]; bi[t - 1] = ti;
                    }
                }
            }
        }
        thr = bd[15];
    };

    // 2 ballots/tile: depth-16 buffer absorbs a 4-group burst (max 16 appends);
    // flush mid-tile and at end.
    auto select = [&](int ct) {
        const float* kp = sKey + selq * CS + half * 32;
        const int base = ct * 64 + half * 32;
#pragma unroll 1
        for (int h2 = 0; h2 < 2; h2++) {
#pragma unroll
            for (int g = h2 * 4; g < h2 * 4 + 4; g++) {
                float4 v = *(const float4*)(kp + g * 4);
                const int ib = base + g * 4;
                if (v.x < thr) { sIBuf[tid * BD + cnt] = ib;     cnt++; }
                if (v.y < thr) { sIBuf[tid * BD + cnt] = ib + 1; cnt++; }
                if (v.z < thr) { sIBuf[tid * BD + cnt] = ib + 2; cnt++; }
                if (v.w < thr) { sIBuf[tid * BD + cnt] = ib + 3; cnt++; }
            }
            if (__any_sync(0xffffffffu, cnt > 0)) flush(ct);
        }
    };

    mma_tile();
#pragma unroll 1
    for (int ct = 1; ct < NT; ct++) {
        __syncthreads();
        loadC(ct);
        select(ct - 1);
        CPWAIT();
        __syncthreads();
        mma_tile();
    }
    __syncthreads();
    select(NT - 1);
    __syncthreads();

    float* mD = sKey;
    int* mI = (int*)((char*)sKey + 64 * 33 * 4);
    {
        const int base = selq * 33 + half * 16;
#pragma unroll
        for (int t = 0; t < 16; t++) { mD[base + t] = bd[t]; mI[base + t] = bi[t]; }
    }
    __syncthreads();
    if (tid < 64) {
        const float* dA = mD + tid * 33;
        const int* iA = mI + tid * 33;
        int ia = 0, ib2 = 16;
        int* o = nbr + ((size_t)b * NN + qbase + tid) * KK;
#pragma unroll
        for (int r = 0; r < 16; r++) {
            float da = dA[ia], db = dA[ib2];
            int xa = iA[ia], xb = iA[ib2];
            bool ta = (da < db) || (da == db && xa < xb);
            o[r] = ta ? xa : xb;
            if (ta) ia++; else ib2++;
        }
    }
}

// ---------------- precompute: register-tiled (4 nodes x 4 h per thread) -----
template <int D>
__global__ __launch_bounds__(256) void precompute_kernel(
    const float* __restrict__ X, const float* __restrict__ w1,
    const float* __restrict__ b1, float* __restrict__ A, float* __restrict__ C) {
    extern __shared__ float PS[];
    float* swd = PS;
    float* swb = PS + D * 64;
    float* sxt = PS + 2 * D * 64;

    const int base = blockIdx.x * 64;
    for (int t = threadIdx.x; t < D * HH; t += 256) {
        float bot = w1[D * HH + t];
        swd[t] = w1[t] - bot;
        swb[t] = bot;
    }
    for (int t = threadIdx.x; t < 64 * D; t += 256) {
        int n = t / D, d = t % D;
        sxt[d * 64 + n] = X[(size_t)base * D + t];
    }
    __syncthreads();

    const int hq = threadIdx.x & 15;
    const int nq = threadIdx.x >> 4;
    const int h0 = hq * 4;
    const float4 bias = *(const float4*)(b1 + h0);

    float a[4][4], c[4][4];
#pragma unroll
    for (int i = 0; i < 4; i++) {
        a[i][0] = bias.x; a[i][1] = bias.y; a[i][2] = bias.z; a[i][3] = bias.w;
        c[i][0] = c[i][1] = c[i][2] = c[i][3] = 0.f;
    }

#pragma unroll
    for (int d = 0; d < D; d++) {
        float4 wd4 = *(const float4*)(swd + d * 64 + h0);
        float4 wb4 = *(const float4*)(swb + d * 64 + h0);
        float4 x4 = *(const float4*)(sxt + d * 64 + nq * 4);
        const float xv[4] = {x4.x, x4.y, x4.z, x4.w};
#pragma unroll
        for (int i = 0; i < 4; i++) {
            a[i][0] = fmaf(xv[i], wd4.x, a[i][0]);
            a[i][1] = fmaf(xv[i], wd4.y, a[i][1]);
            a[i][2] = fmaf(xv[i], wd4.z, a[i][2]);
            a[i][3] = fmaf(xv[i], wd4.w, a[i][3]);
            c[i][0] = fmaf(xv[i], wb4.x, c[i][0]);
            c[i][1] = fmaf(xv[i], wb4.y, c[i][1]);
            c[i][2] = fmaf(xv[i], wb4.z, c[i][2]);
            c[i][3] = fmaf(xv[i], wb4.w, c[i][3]);
        }
    }
#pragma unroll
    for (int i = 0; i < 4; i++) {
        const size_t row = (size_t)(base + nq * 4 + i) * HH + h0;
        *(float4*)(A + row) = make_float4(a[i][0], a[i][1], a[i][2], a[i][3]);
        *(float4*)(C + row) = make_float4(c[i][0], c[i][1], c[i][2], c[i][3]);
    }
}

// ---------------- edge aggregate + output GEMM (64 nodes/block) -------------
// EMIT: also write fp16 features + squared norms for the next layer's kNN.
template <bool EMIT>
__global__ __launch_bounds__(256) void edge_agg_kernel(
    const int* __restrict__ nbr, const float* __restrict__ A,
    const float* __restrict__ C, const float* __restrict__ wo,
    const float* __restrict__ bo, float* __restrict__ out,
    __half* __restrict__ xh, float* __restrict__ sq) {
    __shared__ float swo[HH * HH];
    __shared__ float S[64 * 68];
    __shared__ int snbr[64 * KK];

    const int base = blockIdx.x * 64;
    for (int t = threadIdx.x; t < HH * HH; t += 256) swo[t] = wo[t];
    for (int t = threadIdx.x; t < 64 * KK; t += 256) snbr[t] = nbr[(size_t)base * KK + t];
    __syncthreads();

    const int hq = threadIdx.x & 15;
    const int nq = threadIdx.x >> 4;
    const int h0 = hq * 4;
    const int bofs = ((base >> 11) << 11);
    const float* Cb = C + (size_t)bofs * HH;

#pragma unroll
    for (int i = 0; i < 4; i++) {
        const int n = nq * 4 + i;
        float4 a4 = *(const float4*)(A + (size_t)(base + n) * HH + h0);
        float sx = 0.f, sy = 0.f, sz = 0.f, sw = 0.f;
#pragma unroll
        for (int k = 0; k < KK; k++) {
            int j = snbr[n * KK + k];
            float4 c4 = *(const float4*)(Cb + (size_t)j * HH + h0);
            sx += fmaxf(a4.x + c4.x, 0.f);
            sy += fmaxf(a4.y + c4.y, 0.f);
            sz += fmaxf(a4.z + c4.z, 0.f);
            sw += fmaxf(a4.w + c4.w, 0.f);
        }
        *(float4*)(S + n * 68 + h0) =
            make_float4(sx * (1.f / KK), sy * (1.f / KK), sz * (1.f / KK), sw * (1.f / KK));
    }
    __syncthreads();

    const float4 b4 = *(const float4*)(bo + h0);
    float o[4][4];
#pragma unroll
    for (int i = 0; i < 4; i++) {
        o[i][0] = b4.x; o[i][1] = b4.y; o[i][2] = b4.z; o[i][3] = b4.w;
    }
#pragma unroll 8
    for (int hh = 0; hh < HH; hh++) {
        float4 w4 = *(const float4*)(swo + hh * HH + h0);
#pragma unroll
        for (int i = 0; i < 4; i++) {
            float sv = S[(nq * 4 + i) * 68 + hh];
            o[i][0] = fmaf(sv, w4.x, o[i][0]);
            o[i][1] = fmaf(sv, w4.y, o[i][1]);
            o[i][2] = fmaf(sv, w4.z, o[i][2]);
            o[i][3] = fmaf(sv, w4.w, o[i][3]);
        }
    }
#pragma unroll
    for (int i = 0; i < 4; i++) {
        const int node = base + nq * 4 + i;
        *(float4*)(out + (size_t)node * HH + h0) =
            make_float4(o[i][0], o[i][1], o[i][2], o[i][3]);
        if (EMIT) {
            __half hv[4];
            float ss = 0.f;
#pragma unroll
            for (int j = 0; j < 4; j++) {
                float v = o[i][j];
                ss = fmaf(v, v, ss);
                hv[j] = __float2half(v);
            }
#pragma unroll
            for (int m = 1; m < 16; m <<= 1)
                ss += __shfl_xor_sync(0xffffffffu, ss, m);
            if (hq == 0) sq[node] = ss;
            *(uint2*)(xh + (size_t)node * HH + h0) = *(uint2*)hv;
        }
    }
}

// ---------------- global mean pool + 2-layer head ---------------------------
__global__ __launch_bounds__(128) void head_kernel(
    const float* __restrict__ Xf, const float* __restrict__ fw1,
    const float* __restrict__ fb1, const float* __restrict__ fw2,
    const float* __restrict__ fb2, float* __restrict__ out) {
    int b = blockIdx.x;
    __shared__ float gp[2][HH];
    __shared__ float gv[HH];
    __shared__ float tv[HH];

    int h = threadIdx.x & 63;
    int half = threadIdx.x >> 6;
    float acc = 0.f;
    for (int n = half; n < NN; n += 2)
        acc += Xf[((size_t)b * NN + n) * HH + h];
    gp[half][h] = acc;
    __syncthreads();
    if (threadIdx.x < HH)
        gv[threadIdx.x] = (gp[0][threadIdx.x] + gp[1][threadIdx.x]) * (1.f / NN);
    __syncthreads();
    if (threadIdx.x < HH) {
        float a = fb1[threadIdx.x];
        for (int p = 0; p < HH; p++)
            a = fmaf(gv[p], fw1[p * HH + threadIdx.x], a);
        tv[threadIdx.x] = fmaxf(a, 0.f);
    }
    __syncthreads();
    float o = fb2[threadIdx.x];
    for (int p = 0; p < HH; p++)
        o = fmaf(tv[p], fw2[p * OUTD + threadIdx.x], o);
    out[b * OUTD + threadIdx.x] = o;
}

// ---------------- launch -----------------------------------------------------
static inline int knn_smem_bytes(int DPv) {
    int QSv = DPv + 8;
    return 2 * 64 * QSv * 2 + 64 * 68 * 4 + 256 + 128 * 16 * 4;
}

extern "C" void kernel_launch(void* const* d_in, const int* in_sizes, int n_in,
                              void* d_out, int out_size) {
    (void)in_sizes; (void)n_in; (void)out_size;
    const float* x = (const float*)d_in[0];
    const float* w1a[3] = {(const float*)d_in[1], (const float*)d_in[5], (const float*)d_in[9]};
    const float* b1a[3] = {(const float*)d_in[2], (const float*)d_in[6], (const float*)d_in[10]};
    const float* woa[3] = {(const float*)d_in[3], (const float*)d_in[7], (const float*)d_in[11]};
    const float* boa[3] = {(const float*)d_in[4], (const float*)d_in[8], (const float*)d_in[12]};
    const float* fw1 = (const float*)d_in[13];
    const float* fb1 = (const float*)d_in[14];
    const float* fw2 = (const float*)d_in[15];
    const float* fb2 = (const float*)d_in[16];

    float *buf0, *buf1, *Ab, *Cb, *sq;
    int* nbr;
    __half* xhi;
    float4* pack;
    cudaGetSymbolAddress((void**)&buf0, g_buf0);
    cudaGetSymbolAddress((void**)&buf1, g_buf1);
    cudaGetSymbolAddress((void**)&Ab, g_A);
    cudaGetSymbolAddress((void**)&Cb, g_C);
    cudaGetSymbolAddress((void**)&nbr, g_nbr);
    cudaGetSymbolAddress((void**)&xhi, g_xhi);
    cudaGetSymbolAddress((void**)&sq, g_sq);
    cudaGetSymbolAddress((void**)&pack, g_pack);

    // one-time side-stream + events (host objects only; no device allocation)
    static cudaStream_t s1 = nullptr;
    static cudaEvent_t evF[3], evJ[3];
    if (!s1) {
        cudaStreamCreateWithFlags(&s1, cudaStreamNonBlocking);
        for (int i = 0; i < 3; i++) {
            cudaEventCreateWithFlags(&evF[i], cudaEventDisableTiming);
            cudaEventCreateWithFlags(&evJ[i], cudaEventDisableTiming);
        }
    }

    const int smem64 = knn_smem_bytes(64);
    const int pre3  = 3 * 3 * HH * (int)sizeof(float);
    const int pre64 = 3 * 64 * HH * (int)sizeof(float);
    cudaFuncSetAttribute(knn_mma_kernel<64>, cudaFuncAttributeMaxDynamicSharedMemorySize, smem64);
    cudaFuncSetAttribute(precompute_kernel<64>, cudaFuncAttributeMaxDynamicSharedMemorySize, pre64);

    const int CONV_G = BB * NN / 128;
    const dim3 kg(NN / 64, BB);
    const int PRE_G = BB * NN / 64;
    const int AGG_G = BB * NN / 64;

    // ---- layer 0 (D = 3): pre3 on side stream overlaps pack3+knn3 ----
    cudaEventRecord(evF[0], 0);
    cudaStreamWaitEvent(s1, evF[0], 0);
    precompute_kernel<3><<<PRE_G, 256, pre3, s1>>>(x, w1a[0], b1a[0], Ab, Cb);
    cudaEventRecord(evJ[0], s1);

    pack3_kernel<<<CONV_G, 128>>>(x, pack);
    knn3_kernel<<<kg, 128>>>(pack, nbr);
    cudaStreamWaitEvent(0, evJ[0], 0);
    edge_agg_kernel<true><<<AGG_G, 256>>>(nbr, Ab, Cb, woa[0], boa[0], buf0, xhi, sq);

    // ---- layer 1: pre64 on side stream overlaps knn64 ----
    cudaEventRecord(evF[1], 0);
    cudaStreamWaitEvent(s1, evF[1], 0);
    precompute_kernel<64><<<PRE_G, 256, pre64, s1>>>(buf0, w1a[1], b1a[1], Ab, Cb);
    cudaEventRecord(evJ[1], s1);

    knn_mma_kernel<64><<<kg, 128, smem64>>>(xhi, sq, nbr);
    cudaStreamWaitEvent(0, evJ[1], 0);
    edge_agg_kernel<true><<<AGG_G, 256>>>(nbr, Ab, Cb, woa[1], boa[1], buf1, xhi, sq);

    // ---- layer 2 ----
    cudaEventRecord(evF[2], 0);
    cudaStreamWaitEvent(s1, evF[2], 0);
    precompute_kernel<64><<<PRE_G, 256, pre64, s1>>>(buf1, w1a[2], b1a[2], Ab, Cb);
    cudaEventRecord(evJ[2], s1);

    knn_mma_kernel<64><<<kg, 128, smem64>>>(xhi, sq, nbr);
    cudaStreamWaitEvent(0, evJ[2], 0);
    edge_agg_kernel<false><<<AGG_G, 256>>>(nbr, Ab, Cb, woa[2], boa[2], buf0, nullptr, nullptr);

    head_kernel<<<BB, 128>>>(buf0, fw1, fb1, fw2, fb2, (float*)d_out);
}